// round 16
// baseline (speedup 1.0000x reference)
#include <cuda_runtime.h>
#include <cuda_bf16.h>
#include <cstdint>
#include <cstddef>

#define BHX    48
#define NTOK   8192
#define DIMX   64
#define MSEL   128
#define SPLITS 16
#define CHUNKS 4
#define EQC    4
#define PITCH  132

// ======================= mma.sync / ldmatrix helpers =======================
__device__ __forceinline__ uint32_t smem_to_u32(const void* p) {
    uint32_t a;
    asm("{ .reg .u64 t; cvta.to.shared.u64 t, %1; cvt.u32.u64 %0, t; }" : "=r"(a) : "l"(p));
    return a;
}
#define LDSM_X4(r0, r1, r2, r3, addr) \
    asm volatile("ldmatrix.sync.aligned.m8n8.x4.shared.b16 {%0,%1,%2,%3}, [%4];" \
                 : "=r"(r0), "=r"(r1), "=r"(r2), "=r"(r3) : "r"(addr))
#define LDSM_X4_T(r0, r1, r2, r3, addr) \
    asm volatile("ldmatrix.sync.aligned.m8n8.x4.trans.shared.b16 {%0,%1,%2,%3}, [%4];" \
                 : "=r"(r0), "=r"(r1), "=r"(r2), "=r"(r3) : "r"(addr))
__device__ __forceinline__ void mma_bf16(float* c, uint32_t a0, uint32_t a1, uint32_t a2, uint32_t a3,
                                         uint32_t b0, uint32_t b1) {
    asm volatile("mma.sync.aligned.m16n8k16.row.col.f32.bf16.bf16.f32 "
                 "{%0,%1,%2,%3}, {%4,%5,%6,%7}, {%8,%9}, {%0,%1,%2,%3};"
                 : "+f"(c[0]), "+f"(c[1]), "+f"(c[2]), "+f"(c[3])
                 : "r"(a0), "r"(a1), "r"(a2), "r"(a3), "r"(b0), "r"(b1));
}
__device__ __forceinline__ void bf16split(float v, __nv_bfloat16& h, __nv_bfloat16& l) {
    h = __float2bfloat16(v);
    l = __float2bfloat16(v - __bfloat162float(h));
}
__device__ __forceinline__ void pack_split2(float x, float y, uint32_t& h, uint32_t& l) {
    __nv_bfloat16 hx, lx, hy, ly;
    bf16split(x, hx, lx); bf16split(y, hy, ly);
    __nv_bfloat162 hb = __halves2bfloat162(hx, hy);
    __nv_bfloat162 lb = __halves2bfloat162(lx, ly);
    h = *reinterpret_cast<uint32_t*>(&hb);
    l = *reinterpret_cast<uint32_t*>(&lb);
}

// ---- swizzled (pad-free) layouts; 96KB/CTA -> 2 CTAs/SM; P lives in registers ----
#define T_A    0
#define T_B    32768
#define T_V    65536
#define T_SMEM 98304

// newton smem: 3 matrices [128 x 136 halves] (272B pitch), hi then lo (+34816)
#define NB_K   0
#define NB_V   69632
#define NB_T   139264
#define NB_SZ  208896

// ======================= scratch =======================
__device__ float d_nc [BHX*MSEL*DIMX];
__device__ float d_nr [BHX*MSEL*DIMX];
__device__ float d_K2m[BHX*MSEL*MSEL];
__device__ float d_Vm0[BHX*MSEL*MSEL];
__device__ float d_Zm [BHX*MSEL*DIMX];
__device__ float d_Wm [BHX*MSEL*DIMX];
__device__ unsigned int d_gmax_bits;
__device__ float d_pmax[BHX*SPLITS*MSEL];
__device__ float d_psum[BHX*SPLITS*MSEL];
__device__ float d_pZ  [(size_t)BHX*SPLITS*MSEL*DIMX];

// ======================= streams/events (created at load, before capture) ==========
static cudaStream_t g_s2;
static cudaEvent_t  g_eA, g_eB;
static bool g_streams_ok = false;
namespace {
struct StreamInit {
    StreamInit() {
        g_streams_ok =
            (cudaStreamCreateWithFlags(&g_s2, cudaStreamNonBlocking) == cudaSuccess) &&
            (cudaEventCreateWithFlags(&g_eA, cudaEventDisableTiming) == cudaSuccess) &&
            (cudaEventCreateWithFlags(&g_eB, cudaEventDisableTiming) == cudaSuccess);
    }
};
static StreamInit g_stream_init;
}

// ======================= SIMT helpers =======================
__device__ __forceinline__ float grp_max(float v) {
    v = fmaxf(v, __shfl_xor_sync(0xffffffffu, v, 8));
    v = fmaxf(v, __shfl_xor_sync(0xffffffffu, v, 4));
    v = fmaxf(v, __shfl_xor_sync(0xffffffffu, v, 2));
    v = fmaxf(v, __shfl_xor_sync(0xffffffffu, v, 1));
    return v;
}
__device__ __forceinline__ float grp_sum(float v) {
    v += __shfl_xor_sync(0xffffffffu, v, 8);
    v += __shfl_xor_sync(0xffffffffu, v, 4);
    v += __shfl_xor_sync(0xffffffffu, v, 2);
    v += __shfl_xor_sync(0xffffffffu, v, 1);
    return v;
}
__device__ __forceinline__ void load_tileT(float* dst, const float* __restrict__ g, int tid) {
    for (int i = tid; i < MSEL*DIMX; i += 256) {
        int m = i >> 6, k = i & 63;
        dst[k*PITCH + m] = g[i];
    }
}
__device__ __forceinline__ void mm128(const float* As, const float* Bs,
                                      float acc[8][8], int ty, int tx) {
#pragma unroll 8
    for (int k = 0; k < DIMX; k++) {
        float4 a0 = *reinterpret_cast<const float4*>(&As[k*PITCH + ty*8]);
        float4 a1 = *reinterpret_cast<const float4*>(&As[k*PITCH + ty*8 + 4]);
        float4 b0 = *reinterpret_cast<const float4*>(&Bs[k*PITCH + tx*8]);
        float4 b1 = *reinterpret_cast<const float4*>(&Bs[k*PITCH + tx*8 + 4]);
        float a[8] = {a0.x,a0.y,a0.z,a0.w,a1.x,a1.y,a1.z,a1.w};
        float b[8] = {b0.x,b0.y,b0.z,b0.w,b1.x,b1.y,b1.z,b1.w};
#pragma unroll
        for (int i = 0; i < 8; i++)
#pragma unroll
            for (int j = 0; j < 8; j++)
                acc[i][j] += a[i] * b[j];
    }
}

// stage [128x64] fp32 -> split bf16 swizzled tile (128B rows, lo at +16384)
__device__ __forceinline__ void stage_sw(char* smem, int offH,
                                         const float* __restrict__ g, int tid) {
#pragma unroll
    for (int k = 0; k < 16; k++) {
        int i = tid + k * 256;
        int r = i >> 5, j = i & 31;
        float2 v = *reinterpret_cast<const float2*>(&g[r*64 + j*2]);
        __nv_bfloat16 h0, l0, h1, l1;
        bf16split(v.x, h0, l0); bf16split(v.y, h1, l1);
        uint32_t b = (uint32_t)(r*128) + (uint32_t)(((((j>>2) ^ (r&7)) << 4)) + ((j&3) << 2));
        *(__nv_bfloat162*)(smem + offH + b)         = __halves2bfloat162(h0, h1);
        *(__nv_bfloat162*)(smem + offH + 16384 + b) = __halves2bfloat162(l0, l1);
    }
}

// ======================= kernel 1: radix-select top-k + sort + gather =======================
__global__ __launch_bounds__(256) void topk_gather(const float* __restrict__ Qg,
                                                   const float* __restrict__ Kg) {
    __shared__ uint32_t uk[NTOK];
    __shared__ unsigned int hist[256];
    __shared__ int sel[MSEL];
    __shared__ int sorted[MSEL];
    __shared__ int sh_b, sh_need, scnt;
    int hh = blockIdx.x, which = blockIdx.y, tid = threadIdx.x;
    const float* src = (which == 0 ? Kg : Qg) + (size_t)hh * NTOK * DIMX;

    if (hh == 0 && which == 0 && tid == 0) d_gmax_bits = 0u;

    for (int i = tid; i < NTOK; i += 256) {
        uint32_t b = __float_as_uint(src[(size_t)i * DIMX]);
        uk[i] = (b & 0x80000000u) ? ~b : (b | 0x80000000u);
    }
    __syncthreads();
    if (tid == 0) uk[0] = 0u;
    __syncthreads();

    uint64_t pref = 0;
    int need = MSEL - 1;
#pragma unroll 1
    for (int L = 0; L < 6; L++) {
        int shift = 40 - 8 * L;
        hist[tid] = 0u;
        __syncthreads();
        for (int i = tid; i < NTOK; i += 256) {
            uint64_t c = ((uint64_t)uk[i] << 16) | (uint32_t)(65535 - i);
            if ((c >> (shift + 8)) == pref)
                atomicAdd(&hist[(uint32_t)(c >> shift) & 0xFFu], 1u);
        }
        __syncthreads();
        if (tid == 0) {
            int acc = 0, b = 255;
            for (; b >= 0; b--) {
                int nb = acc + (int)hist[b];
                if (nb >= need) break;
                acc = nb;
            }
            sh_b = b; sh_need = need - acc;
        }
        __syncthreads();
        pref = (pref << 8) | (uint32_t)sh_b;
        need = sh_need;
        __syncthreads();
    }
    uint64_t T = pref;

    if (tid == 0) scnt = 0;
    __syncthreads();
    for (int i = tid; i < NTOK; i += 256) {
        uint64_t c = ((uint64_t)uk[i] << 16) | (uint32_t)(65535 - i);
        if (c >= T) { int p = atomicAdd(&scnt, 1); sel[p] = i; }
    }
    __syncthreads();
    if (tid == 0) sel[MSEL - 1] = 0;
    __syncthreads();

    if (tid < MSEL) {
        int my = sel[tid], rank = 0;
        for (int j = 0; j < MSEL; j++) rank += (sel[j] < my);
        sorted[rank] = my;
    }
    __syncthreads();

    float* dst = (which == 0 ? d_nc : d_nr) + (size_t)hh * MSEL * DIMX;
    for (int i = tid; i < MSEL * DIMX; i += 256) {
        int p = i >> 6, d = i & 63;
        dst[i] = src[(size_t)sorted[p] * DIMX + d];
    }
}

// ======================= kernel 2: kernel_2 = softmax(nr @ nc^T), colsum max =======================
__global__ __launch_bounds__(256) void mker() {
    extern __shared__ float sm[];
    float* As = sm;
    float* Bs = sm + DIMX * PITCH;
    float* cs = sm + 2 * DIMX * PITCH;
    int hh = blockIdx.x, tid = threadIdx.x;
    int ty = tid >> 4, tx = tid & 15;
    load_tileT(As, d_nr + (size_t)hh * MSEL * DIMX, tid);
    load_tileT(Bs, d_nc + (size_t)hh * MSEL * DIMX, tid);
    if (tid < MSEL) cs[tid] = 0.f;
    __syncthreads();

    float acc[8][8] = {};
    mm128(As, Bs, acc, ty, tx);

    float* K2h = d_K2m + (size_t)hh * MSEL * MSEL;
    float colp[8] = {};
#pragma unroll
    for (int i = 0; i < 8; i++) {
        float mx = acc[i][0];
#pragma unroll
        for (int j = 1; j < 8; j++) mx = fmaxf(mx, acc[i][j]);
        mx = grp_max(mx);
        float s = 0.f;
#pragma unroll
        for (int j = 0; j < 8; j++) { acc[i][j] = __expf(acc[i][j] - mx); s += acc[i][j]; }
        s = grp_sum(s);
        float inv = 1.f / s;
#pragma unroll
        for (int j = 0; j < 8; j++) {
            float p = acc[i][j] * inv;
            K2h[(ty*8 + i) * MSEL + tx*8 + j] = p;
            colp[j] += p;
        }
    }
#pragma unroll
    for (int j = 0; j < 8; j++) atomicAdd(&cs[tx*8 + j], colp[j]);
    __syncthreads();
    if (tid < MSEL) atomicMax(&d_gmax_bits, __float_as_uint(cs[tid]));
}

// ======================= MMA1 + online softmax + MMA2 tile body (P in registers) ==========
__device__ __forceinline__ void attn_tile_reg(uint32_t sb, int wid, int lane,
                                              float C2[8][4],
                                              float& m0, float& m1, float& s0, float& s1) {
    float C1[16][4] = {};
    int aRow = wid*16 + (lane & 15);
    int aq = lane >> 4, arb = aRow & 7;
    uint32_t aBase = sb + T_A + aRow*128;
    int bRow0 = (lane & 7) + ((lane >> 4) << 3);
    int bq = (lane >> 3) & 1, brb = bRow0 & 7;
    uint32_t bBase = sb + T_B + bRow0*128;

#pragma unroll
    for (int ks = 0; ks < 4; ks++) {
        uint32_t aA = aBase + ((uint32_t)(((2*ks) | aq) ^ arb) << 4);
        uint32_t ah0, ah1, ah2, ah3, al0, al1, al2, al3;
        LDSM_X4(ah0, ah1, ah2, ah3, aA);
        LDSM_X4(al0, al1, al2, al3, aA + 16384);
#pragma unroll
        for (int p = 0; p < 8; p++) {
            uint32_t bA = bBase + p*2048 + ((uint32_t)(((2*ks) | bq) ^ brb) << 4);
            uint32_t bh0, bh1, bh2, bh3, bl0, bl1, bl2, bl3;
            LDSM_X4(bh0, bh1, bh2, bh3, bA);
            LDSM_X4(bl0, bl1, bl2, bl3, bA + 16384);
            mma_bf16(C1[2*p],   ah0, ah1, ah2, ah3, bh0, bh1);
            mma_bf16(C1[2*p+1], ah0, ah1, ah2, ah3, bh2, bh3);
            mma_bf16(C1[2*p],   ah0, ah1, ah2, ah3, bl0, bl1);
            mma_bf16(C1[2*p+1], ah0, ah1, ah2, ah3, bl2, bl3);
            mma_bf16(C1[2*p],   al0, al1, al2, al3, bh0, bh1);
            mma_bf16(C1[2*p+1], al0, al1, al2, al3, bh2, bh3);
        }
    }

    float cx0 = -3.402823466e38f, cx1 = -3.402823466e38f;
#pragma unroll
    for (int t = 0; t < 16; t++) {
        cx0 = fmaxf(cx0, fmaxf(C1[t][0], C1[t][1]));
        cx1 = fmaxf(cx1, fmaxf(C1[t][2], C1[t][3]));
    }
    cx0 = fmaxf(cx0, __shfl_xor_sync(0xffffffffu, cx0, 1));
    cx0 = fmaxf(cx0, __shfl_xor_sync(0xffffffffu, cx0, 2));
    cx1 = fmaxf(cx1, __shfl_xor_sync(0xffffffffu, cx1, 1));
    cx1 = fmaxf(cx1, __shfl_xor_sync(0xffffffffu, cx1, 2));

    float mn0 = fmaxf(m0, cx0), mn1 = fmaxf(m1, cx1);
    float f0 = __expf(m0 - mn0), f1 = __expf(m1 - mn1);
    float su0 = 0.f, su1 = 0.f;
#pragma unroll
    for (int t = 0; t < 16; t++) {
        C1[t][0] = __expf(C1[t][0] - mn0); C1[t][1] = __expf(C1[t][1] - mn0);
        C1[t][2] = __expf(C1[t][2] - mn1); C1[t][3] = __expf(C1[t][3] - mn1);
        su0 += C1[t][0] + C1[t][1];
        su1 += C1[t][2] + C1[t][3];
    }
    su0 += __shfl_xor_sync(0xffffffffu, su0, 1);
    su0 += __shfl_xor_sync(0xffffffffu, su0, 2);
    su1 += __shfl_xor_sync(0xffffffffu, su1, 1);
    su1 += __shfl_xor_sync(0xffffffffu, su1, 2);
    s0 = s0 * f0 + su0;  s1 = s1 * f1 + su1;
    m0 = mn0;            m1 = mn1;
#pragma unroll
    for (int t = 0; t < 8; t++) {
        C2[t][0] *= f0; C2[t][1] *= f0;
        C2[t][2] *= f1; C2[t][3] *= f1;
    }

    // FA2 register trick: C1 fragments are MMA2 A-fragments directly.
    uint32_t pA0[16], pA1[16], lA0[16], lA1[16];
#pragma unroll
    for (int t = 0; t < 16; t++) {
        pack_split2(C1[t][0], C1[t][1], pA0[t], lA0[t]);
        pack_split2(C1[t][2], C1[t][3], pA1[t], lA1[t]);
    }

    int vRow0 = lane & 15;
    int vq = lane >> 4, vrb = vRow0 & 7;
    uint32_t vBase = sb + T_V + vRow0*128;
#pragma unroll
    for (int ks = 0; ks < 8; ks++) {
        uint32_t ah0 = pA0[2*ks], ah1 = pA1[2*ks], ah2 = pA0[2*ks+1], ah3 = pA1[2*ks+1];
        uint32_t al0 = lA0[2*ks], al1 = lA1[2*ks], al2 = lA0[2*ks+1], al3 = lA1[2*ks+1];
#pragma unroll
        for (int p = 0; p < 4; p++) {
            uint32_t vA = vBase + ks*2048 + ((uint32_t)(((2*p) | vq) ^ vrb) << 4);
            uint32_t vh0, vh1, vh2, vh3, vl0, vl1, vl2, vl3;
            LDSM_X4_T(vh0, vh1, vh2, vh3, vA);
            LDSM_X4_T(vl0, vl1, vl2, vl3, vA + 16384);
            mma_bf16(C2[2*p],   ah0, ah1, ah2, ah3, vh0, vh1);
            mma_bf16(C2[2*p+1], ah0, ah1, ah2, ah3, vh2, vh3);
            mma_bf16(C2[2*p],   ah0, ah1, ah2, ah3, vl0, vl1);
            mma_bf16(C2[2*p+1], ah0, ah1, ah2, ah3, vl2, vl3);
            mma_bf16(C2[2*p],   al0, al1, al2, al3, vh0, vh1);
            mma_bf16(C2[2*p+1], al0, al1, al2, al3, vh2, vh3);
        }
    }
}

// ======================= kernel 3: flash over 4 chunks, fine-grained split grid ==========
__global__ __launch_bounds__(256, 2) void r1ker(const float* __restrict__ Kg,
                                                const float* __restrict__ Vg) {
    extern __shared__ char smem[];
    uint32_t sb = smem_to_u32(smem);
    int hh = blockIdx.x, s = blockIdx.y, tid = threadIdx.x;
    int wid = tid >> 5, lane = tid & 31;

    const float* Kbase = Kg + ((size_t)hh * NTOK + (size_t)s * CHUNKS * MSEL) * DIMX;
    const float* Vbase = Vg + ((size_t)hh * NTOK + (size_t)s * CHUNKS * MSEL) * DIMX;

    stage_sw(smem, T_A, d_nr + (size_t)hh * MSEL * DIMX, tid);   // once — never clobbered

    float C2[8][4] = {};
    float m0 = -3.402823466e38f, m1 = -3.402823466e38f, s0 = 0.f, s1 = 0.f;

#pragma unroll 1
    for (int c = 0; c < CHUNKS; c++) {
        if (c) __syncthreads();
        stage_sw(smem, T_B, Kbase + (size_t)c * MSEL * DIMX, tid);
        stage_sw(smem, T_V, Vbase + (size_t)c * MSEL * DIMX, tid);
        __syncthreads();
        attn_tile_reg(sb, wid, lane, C2, m0, m1, s0, s1);
    }

    size_t base = (size_t)(hh * SPLITS + s) * MSEL;
    int grow0 = wid*16 + (lane >> 2);
    int pcol = (lane & 3) * 2;
    if ((lane & 3) == 0) {
        d_pmax[base + grow0]     = m0;  d_psum[base + grow0]     = s0;
        d_pmax[base + grow0 + 8] = m1;  d_psum[base + grow0 + 8] = s1;
    }
    float* z0 = d_pZ + (base + grow0) * DIMX;
    float* z1 = z0 + 8 * DIMX;
#pragma unroll
    for (int t = 0; t < 8; t++) {
        *reinterpret_cast<float2*>(&z0[t*8 + pcol]) = make_float2(C2[t][0], C2[t][1]);
        *reinterpret_cast<float2*>(&z1[t*8 + pcol]) = make_float2(C2[t][2], C2[t][3]);
    }
}

// ======================= kernel 4: combine splits =======================
__global__ void combiner() {
    int hh = blockIdx.x;
    int r  = blockIdx.y * 16 + threadIdx.y;
    int d  = threadIdx.x * 4;
    const float* pm = d_pmax + (size_t)hh * SPLITS * MSEL;
    const float* ps = d_psum + (size_t)hh * SPLITS * MSEL;
    float M = -3.402823466e38f;
#pragma unroll
    for (int s = 0; s < SPLITS; s++) M = fmaxf(M, pm[s * MSEL + r]);
    float l = 0.f;
    float4 z = make_float4(0.f, 0.f, 0.f, 0.f);
#pragma unroll
    for (int s = 0; s < SPLITS; s++) {
        float w = __expf(pm[s * MSEL + r] - M);
        l += ps[s * MSEL + r] * w;
        float4 pz = *reinterpret_cast<const float4*>(
            &d_pZ[((size_t)(hh * SPLITS + s) * MSEL + r) * DIMX + d]);
        z.x += w * pz.x; z.y += w * pz.y; z.z += w * pz.z; z.w += w * pz.w;
    }
    float inv = 1.f / l;
    *reinterpret_cast<float4*>(&d_Zm[((size_t)hh * MSEL + r) * DIMX + d]) =
        make_float4(z.x * inv, z.y * inv, z.z * inv, z.w * inv);
}

// ======================= Newton-Schulz: single persistent 512-thread TC kernel ==========
__device__ __forceinline__ void stage_split128_512(char* smem, int off,
                                                   const float* __restrict__ g, int tid) {
#pragma unroll
    for (int k = 0; k < 16; k++) {
        int i = tid + k * 512;
        int r = i >> 6, c2 = (i & 63) * 2;
        float2 v = *reinterpret_cast<const float2*>(&g[r*128 + c2]);
        __nv_bfloat16 h0, l0, h1, l1;
        bf16split(v.x, h0, l0); bf16split(v.y, h1, l1);
        int ob = r*272 + c2*2;
        *(__nv_bfloat162*)(smem + off + ob)         = __halves2bfloat162(h0, h1);
        *(__nv_bfloat162*)(smem + off + 34816 + ob) = __halves2bfloat162(l0, l1);
    }
}
__device__ __forceinline__ void stage_split128T(char* smem, int off,
                                                const float* __restrict__ g, float inv, int tid) {
#pragma unroll
    for (int k = 0; k < 16; k++) {
        int i = tid + k * 512;
        int r = i >> 6, c2 = (i & 63) * 2;
        float vx = g[c2*128 + r] * inv;
        float vy = g[(c2+1)*128 + r] * inv;
        __nv_bfloat16 h0, l0, h1, l1;
        bf16split(vx, h0, l0); bf16split(vy, h1, l1);
        int ob = r*272 + c2*2;
        *(__nv_bfloat162*)(smem + off + ob)         = __halves2bfloat162(h0, h1);
        *(__nv_bfloat162*)(smem + off + 34816 + ob) = __halves2bfloat162(l0, l1);
    }
}

__device__ __forceinline__ void mm_tc512(uint32_t sb, int offA, int offB,
                                         int rg, int cg, int lane, float C[8][4]) {
#pragma unroll
    for (int t = 0; t < 8; t++) { C[t][0] = 0.f; C[t][1] = 0.f; C[t][2] = 0.f; C[t][3] = 0.f; }
    uint32_t aH = sb + offA + (rg*16 + (lane & 15))*272 + ((lane >> 4) << 4);
    uint32_t aL = aH + 34816;
    uint32_t bH = sb + offB + (lane & 15)*272 + ((lane >> 4) << 4) + cg*128;
    uint32_t bL = bH + 34816;
#pragma unroll
    for (int ks = 0; ks < 8; ks++) {
        uint32_t ah0, ah1, ah2, ah3, al0, al1, al2, al3;
        LDSM_X4(ah0, ah1, ah2, ah3, aH + ks*32);
        LDSM_X4(al0, al1, al2, al3, aL + ks*32);
#pragma unroll
        for (int p = 0; p < 4; p++) {
            uint32_t bh0, bh1, bh2, bh3, bl0, bl1, bl2, bl3;
            LDSM_X4_T(bh0, bh1, bh2, bh3, bH + ks*4352 + p*32);
            LDSM_X4_T(bl0, bl1, bl2, bl3, bL + ks*4352 + p*32);
            mma_bf16(C[2*p],   ah0, ah1, ah2, ah3, bh0, bh1);
            mma_bf16(C[2*p+1], ah0, ah1, ah2, ah3, bh2, bh3);
            mma_bf16(C[2*p],   ah0, ah1, ah2, ah3, bl0, bl1);
            mma_bf16(C[2*p+1], ah0, ah1, ah2, ah3, bl2, bl3);
            mma_bf16(C[2*p],   al0, al1, al2, al3, bh0, bh1);
            mma_bf16(C[2*p+1], al0, al1, al2, al3, bh2, bh3);
        }
    }
}

__device__ __forceinline__ void store_split512(char* smem, int off, int rg, int cg, int lane,
                                               const float C[8][4]) {
    int r0 = rg*16 + (lane >> 2);
    int cb0 = (lane & 3) * 2;
#pragma unroll
    for (int t = 0; t < 8; t++) {
        int cb = (cg*64 + t*8 + cb0) * 2;
        __nv_bfloat16 h0, l0, h1, l1;
        bf16split(C[t][0], h0, l0); bf16split(C[t][1], h1, l1);
        *(__nv_bfloat162*)(smem + off + r0*272 + cb)         = __halves2bfloat162(h0, h1);
        *(__nv_bfloat162*)(smem + off + 34816 + r0*272 + cb) = __halves2bfloat162(l0, l1);
        bf16split(C[t][2], h0, l0); bf16split(C[t][3], h1, l1);
        *(__nv_bfloat162*)(smem + off + (r0+8)*272 + cb)         = __halves2bfloat162(h0, h1);
        *(__nv_bfloat162*)(smem + off + 34816 + (r0+8)*272 + cb) = __halves2bfloat162(l0, l1);
    }
}
__device__ __forceinline__ float read_split(const char* smem, int off, int r, int c) {
    float h = __bfloat162float(*(const __nv_bfloat16*)(smem + off + r*272 + c*2));
    float l = __bfloat162float(*(const __nv_bfloat16*)(smem + off + 34816 + r*272 + c*2));
    return h + l;
}

__global__ __launch_bounds__(512) void newton_persist() {
    extern __shared__ char smem[];
    uint32_t sb = smem_to_u32(smem);
    int hh = blockIdx.x, tid = threadIdx.x;
    int wid = tid >> 5, lane = tid & 31;
    int rg = wid & 7, cg = wid >> 3;
    float R[8][4];
    const float* K2g = d_K2m + (size_t)hh * MSEL * MSEL;
    float inv = 1.f / __uint_as_float(d_gmax_bits);

    stage_split128T(smem, NB_V, K2g, inv, tid);

#pragma unroll 1
    for (int it = 0; it < 6; it++) {
        stage_split128_512(smem, NB_K, K2g, tid);
        __syncthreads();

        mm_tc512(sb, NB_K, NB_V, rg, cg, lane, R);  // KV = K2 @ Vm
        __syncthreads();
        store_split512(smem, NB_K, rg, cg, lane, R);
        __syncthreads();

        mm_tc512(sb, NB_K, NB_K, rg, cg, lane, R);  // P2 = KV @ KV
        __syncthreads();
        store_split512(smem, NB_T, rg, cg, lane, R);
        __syncthreads();

        mm_tc512(sb, NB_K, NB_T, rg, cg, lane, R);  // P3 = KV @ P2
        {
            int r0 = rg*16 + (lane >> 2);
            int cb0 = (lane & 3) * 2;
#pragma unroll
            for (int t = 0; t < 8; t++) {
                int c = cg*64 + t*8 + cb0;
#pragma unroll
                for (int j = 0; j < 4; j++) {
                    int rr = r0 + ((j >> 1) << 3);
                    int cc = c + (j & 1);
                    float kv = read_split(smem, NB_K, rr, cc);
                    float p2 = read_split(smem, NB_T, rr, cc);
                    float e = -15.f*kv + 7.f*p2 - R[t][j];
                    if (rr == cc) e += 13.f;
                    R[t][j] = e;
                }
            }
        }
        __syncthreads();
        store_split512(smem, NB_T, rg, cg, lane, R);
        __syncthreads();

        mm_tc512(sb, NB_V, NB_T, rg, cg, lane, R);  // Vm @ E
        __syncthreads();
#pragma unroll
        for (int t = 0; t < 8; t++) {
            R[t][0] *= 0.25f; R[t][1] *= 0.25f; R[t][2] *= 0.25f; R[t][3] *= 0.25f;
        }
        store_split512(smem, NB_V, rg, cg, lane, R);
        if (it == 5) {
            float* out = d_Vm0 + (size_t)hh * MSEL * MSEL;
            int r0 = rg*16 + (lane >> 2);
            int cb0 = (lane & 3) * 2;
#pragma unroll
            for (int t = 0; t < 8; t++) {
                int c = cg*64 + t*8 + cb0;
                *reinterpret_cast<float2*>(&out[r0*128 + c]) = make_float2(R[t][0], R[t][1]);
                *reinterpret_cast<float2*>(&out[(r0+8)*128 + c]) = make_float2(R[t][2], R[t][3]);
            }
        }
        __syncthreads();
    }
}

// W = Vm_final @ Z  (128x64), grid (48, 2)
__global__ __launch_bounds__(256) void wker() {
    __shared__ float As[32][65];
    __shared__ float Bs[32][65];
    int hh = blockIdx.x;
    const float* Vm = d_Vm0 + (size_t)hh * MSEL * MSEL;
    const float* Z  = d_Zm + (size_t)hh * MSEL * DIMX;
    int r0 = blockIdx.y * 64;
    int tid = threadIdx.x, ty = tid >> 4, tx = tid & 15;
    float acc[4][4] = {};
    for (int kc = 0; kc < MSEL; kc += 32) {
        for (int i = tid; i < 2048; i += 256) {
            int m = i >> 5, k = i & 31;
            As[k][m] = Vm[(r0 + m) * MSEL + kc + k];
        }
        for (int i = tid; i < 2048; i += 256) {
            int k = i >> 6, n = i & 63;
            Bs[k][n] = Z[(kc + k) * DIMX + n];
        }
        __syncthreads();
#pragma unroll 8
        for (int k = 0; k < 32; k++) {
            float a[4], b[4];
#pragma unroll
            for (int i = 0; i < 4; i++) a[i] = As[k][ty*4 + i];
#pragma unroll
            for (int j = 0; j < 4; j++) b[j] = Bs[k][tx*4 + j];
#pragma unroll
            for (int i = 0; i < 4; i++)
#pragma unroll
                for (int j = 0; j < 4; j++)
                    acc[i][j] += a[i] * b[j];
        }
        __syncthreads();
    }
#pragma unroll
    for (int i = 0; i < 4; i++)
#pragma unroll
        for (int j = 0; j < 4; j++)
            d_Wm[(size_t)hh * MSEL * DIMX + (r0 + ty*4 + i) * DIMX + tx*4 + j] = acc[i][j];
}

// ======================= final: X = softmax(Q @ nc^T) @ W, fine-grained grid ==========
__global__ __launch_bounds__(256, 2) void eker(const float* __restrict__ Qg,
                                               float* __restrict__ Xg) {
    extern __shared__ char smem[];
    uint32_t sb = smem_to_u32(smem);
    int hh = blockIdx.x, tid = threadIdx.x;
    int wid = tid >> 5, lane = tid & 31;

    const float* Qbase = Qg + ((size_t)hh * NTOK + (size_t)blockIdx.y * EQC * MSEL) * DIMX;

    stage_sw(smem, T_B, d_nc + (size_t)hh * MSEL * DIMX, tid);   // once
    stage_sw(smem, T_V, d_Wm + (size_t)hh * MSEL * DIMX, tid);   // once

    int grow0 = wid*16 + (lane >> 2);
    int pcol = (lane & 3) * 2;

#pragma unroll 1
    for (int c = 0; c < EQC; c++) {
        if (c) __syncthreads();
        stage_sw(smem, T_A, Qbase + (size_t)c * MSEL * DIMX, tid);
        __syncthreads();

        float C2[8][4] = {};
        float m0 = -3.402823466e38f, m1 = -3.402823466e38f, s0 = 0.f, s1 = 0.f;
        attn_tile_reg(sb, wid, lane, C2, m0, m1, s0, s1);

        float rinv0 = 1.f / s0, rinv1 = 1.f / s1;
        float* x0 = Xg + ((size_t)hh * NTOK + (size_t)(blockIdx.y * EQC + c) * MSEL + grow0) * DIMX;
        float* x1 = x0 + 8 * DIMX;
#pragma unroll
        for (int t = 0; t < 8; t++) {
            *reinterpret_cast<float2*>(&x0[t*8 + pcol]) =
                make_float2(C2[t][0] * rinv0, C2[t][1] * rinv0);
            *reinterpret_cast<float2*>(&x1[t*8 + pcol]) =
                make_float2(C2[t][2] * rinv1, C2[t][3] * rinv1);
        }
    }
}

// ======================= launch (two-stream fork/join DAG) =======================
extern "C" void kernel_launch(void* const* d_in, const int* in_sizes, int n_in,
                              void* d_out, int out_size) {
    const float* Q = (const float*)d_in[0];
    const float* K = (const float*)d_in[1];
    const float* V = (const float*)d_in[2];
    float* X = (float*)d_out;

    const int SMEM_MK = (2 * DIMX * PITCH + MSEL) * 4;
    cudaFuncSetAttribute(mker,           cudaFuncAttributeMaxDynamicSharedMemorySize, SMEM_MK);
    cudaFuncSetAttribute(r1ker,          cudaFuncAttributeMaxDynamicSharedMemorySize, T_SMEM);
    cudaFuncSetAttribute(eker,           cudaFuncAttributeMaxDynamicSharedMemorySize, T_SMEM);
    cudaFuncSetAttribute(newton_persist, cudaFuncAttributeMaxDynamicSharedMemorySize, NB_SZ);

    bool fork = g_streams_ok;
    cudaStream_t sB = fork ? g_s2 : (cudaStream_t)0;

    topk_gather<<<dim3(BHX, 2), 256>>>(Q, K);

    if (fork) {
        cudaEventRecord(g_eA, 0);
        cudaStreamWaitEvent(sB, g_eA, 0);
    }
    // branch B: mker -> persistent newton
    mker<<<BHX, 256, SMEM_MK, sB>>>();
    newton_persist<<<BHX, 512, NB_SZ, sB>>>();
    if (fork) cudaEventRecord(g_eB, sB);

    // branch A: r1ker -> combiner, concurrent with branch B
    r1ker<<<dim3(BHX, SPLITS), 256, T_SMEM>>>(K, V);
    combiner<<<dim3(BHX, 8), dim3(16, 16)>>>();

    if (fork) cudaStreamWaitEvent(0, g_eB, 0);
    wker<<<dim3(BHX, 2), 256>>>();
    eker<<<dim3(BHX, NTOK / MSEL / EQC), 256, T_SMEM>>>(Q, X);
}

// round 17
// speedup vs baseline: 1.0286x; 1.0286x over previous
#include <cuda_runtime.h>
#include <cuda_bf16.h>
#include <cstdint>
#include <cstddef>

#define BHX    48
#define NTOK   8192
#define DIMX   64
#define MSEL   128
#define SPLITS 8
#define CHUNKS 8
#define EQC    8
#define PITCH  132

// ======================= mma.sync / ldmatrix helpers =======================
__device__ __forceinline__ uint32_t smem_to_u32(const void* p) {
    uint32_t a;
    asm("{ .reg .u64 t; cvta.to.shared.u64 t, %1; cvt.u32.u64 %0, t; }" : "=r"(a) : "l"(p));
    return a;
}
#define LDSM_X4(r0, r1, r2, r3, addr) \
    asm volatile("ldmatrix.sync.aligned.m8n8.x4.shared.b16 {%0,%1,%2,%3}, [%4];" \
                 : "=r"(r0), "=r"(r1), "=r"(r2), "=r"(r3) : "r"(addr))
#define LDSM_X4_T(r0, r1, r2, r3, addr) \
    asm volatile("ldmatrix.sync.aligned.m8n8.x4.trans.shared.b16 {%0,%1,%2,%3}, [%4];" \
                 : "=r"(r0), "=r"(r1), "=r"(r2), "=r"(r3) : "r"(addr))
__device__ __forceinline__ void mma_bf16(float* c, uint32_t a0, uint32_t a1, uint32_t a2, uint32_t a3,
                                         uint32_t b0, uint32_t b1) {
    asm volatile("mma.sync.aligned.m16n8k16.row.col.f32.bf16.bf16.f32 "
                 "{%0,%1,%2,%3}, {%4,%5,%6,%7}, {%8,%9}, {%0,%1,%2,%3};"
                 : "+f"(c[0]), "+f"(c[1]), "+f"(c[2]), "+f"(c[3])
                 : "r"(a0), "r"(a1), "r"(a2), "r"(a3), "r"(b0), "r"(b1));
}
__device__ __forceinline__ void bf16split(float v, __nv_bfloat16& h, __nv_bfloat16& l) {
    h = __float2bfloat16(v);
    l = __float2bfloat16(v - __bfloat162float(h));
}
__device__ __forceinline__ void pack_split2(float x, float y, uint32_t& h, uint32_t& l) {
    __nv_bfloat16 hx, lx, hy, ly;
    bf16split(x, hx, lx); bf16split(y, hy, ly);
    __nv_bfloat162 hb = __halves2bfloat162(hx, hy);
    __nv_bfloat162 lb = __halves2bfloat162(lx, ly);
    h = *reinterpret_cast<uint32_t*>(&hb);
    l = *reinterpret_cast<uint32_t*>(&lb);
}

// ---- swizzled (pad-free) layouts; 96KB/CTA -> 2 CTAs/SM; P lives in registers ----
#define T_A    0
#define T_B    32768
#define T_V    65536
#define T_SMEM 98304

// newton smem: 3 matrices [128 x 136 halves] (272B pitch), hi then lo (+34816)
#define NB_K   0
#define NB_V   69632
#define NB_T   139264
#define NB_SZ  208896

// ======================= scratch =======================
__device__ float d_nc [BHX*MSEL*DIMX];
__device__ float d_nr [BHX*MSEL*DIMX];
__device__ float d_K2m[BHX*MSEL*MSEL];
__device__ float d_Vm0[BHX*MSEL*MSEL];
__device__ float d_Zm [BHX*MSEL*DIMX];
__device__ float d_Wm [BHX*MSEL*DIMX];
__device__ unsigned int d_gmax_bits;
__device__ float d_pmax[BHX*SPLITS*MSEL];
__device__ float d_psum[BHX*SPLITS*MSEL];
__device__ float d_pZ  [(size_t)BHX*SPLITS*MSEL*DIMX];

// ======================= streams/events (created at load, before capture) ==========
static cudaStream_t g_s2;
static cudaEvent_t  g_eA, g_eB;
static bool g_streams_ok = false;
namespace {
struct StreamInit {
    StreamInit() {
        g_streams_ok =
            (cudaStreamCreateWithFlags(&g_s2, cudaStreamNonBlocking) == cudaSuccess) &&
            (cudaEventCreateWithFlags(&g_eA, cudaEventDisableTiming) == cudaSuccess) &&
            (cudaEventCreateWithFlags(&g_eB, cudaEventDisableTiming) == cudaSuccess);
    }
};
static StreamInit g_stream_init;
}

// ======================= SIMT helpers =======================
__device__ __forceinline__ float grp_max(float v) {
    v = fmaxf(v, __shfl_xor_sync(0xffffffffu, v, 8));
    v = fmaxf(v, __shfl_xor_sync(0xffffffffu, v, 4));
    v = fmaxf(v, __shfl_xor_sync(0xffffffffu, v, 2));
    v = fmaxf(v, __shfl_xor_sync(0xffffffffu, v, 1));
    return v;
}
__device__ __forceinline__ float grp_sum(float v) {
    v += __shfl_xor_sync(0xffffffffu, v, 8);
    v += __shfl_xor_sync(0xffffffffu, v, 4);
    v += __shfl_xor_sync(0xffffffffu, v, 2);
    v += __shfl_xor_sync(0xffffffffu, v, 1);
    return v;
}
__device__ __forceinline__ void load_tileT(float* dst, const float* __restrict__ g, int tid) {
    for (int i = tid; i < MSEL*DIMX; i += 256) {
        int m = i >> 6, k = i & 63;
        dst[k*PITCH + m] = g[i];
    }
}
__device__ __forceinline__ void mm128(const float* As, const float* Bs,
                                      float acc[8][8], int ty, int tx) {
#pragma unroll 8
    for (int k = 0; k < DIMX; k++) {
        float4 a0 = *reinterpret_cast<const float4*>(&As[k*PITCH + ty*8]);
        float4 a1 = *reinterpret_cast<const float4*>(&As[k*PITCH + ty*8 + 4]);
        float4 b0 = *reinterpret_cast<const float4*>(&Bs[k*PITCH + tx*8]);
        float4 b1 = *reinterpret_cast<const float4*>(&Bs[k*PITCH + tx*8 + 4]);
        float a[8] = {a0.x,a0.y,a0.z,a0.w,a1.x,a1.y,a1.z,a1.w};
        float b[8] = {b0.x,b0.y,b0.z,b0.w,b1.x,b1.y,b1.z,b1.w};
#pragma unroll
        for (int i = 0; i < 8; i++)
#pragma unroll
            for (int j = 0; j < 8; j++)
                acc[i][j] += a[i] * b[j];
    }
}

// stage [128x64] fp32 -> split bf16 swizzled tile (128B rows, lo at +16384)
__device__ __forceinline__ void stage_sw(char* smem, int offH,
                                         const float* __restrict__ g, int tid) {
#pragma unroll
    for (int k = 0; k < 16; k++) {
        int i = tid + k * 256;
        int r = i >> 5, j = i & 31;
        float2 v = *reinterpret_cast<const float2*>(&g[r*64 + j*2]);
        __nv_bfloat16 h0, l0, h1, l1;
        bf16split(v.x, h0, l0); bf16split(v.y, h1, l1);
        uint32_t b = (uint32_t)(r*128) + (uint32_t)(((((j>>2) ^ (r&7)) << 4)) + ((j&3) << 2));
        *(__nv_bfloat162*)(smem + offH + b)         = __halves2bfloat162(h0, h1);
        *(__nv_bfloat162*)(smem + offH + 16384 + b) = __halves2bfloat162(l0, l1);
    }
}

// ======================= kernel 1: radix-select top-k + sort + gather =======================
__global__ __launch_bounds__(256) void topk_gather(const float* __restrict__ Qg,
                                                   const float* __restrict__ Kg) {
    __shared__ uint32_t uk[NTOK];
    __shared__ unsigned int hist[256];
    __shared__ int sel[MSEL];
    __shared__ int sorted[MSEL];
    __shared__ int sh_b, sh_need, scnt;
    int hh = blockIdx.x, which = blockIdx.y, tid = threadIdx.x;
    const float* src = (which == 0 ? Kg : Qg) + (size_t)hh * NTOK * DIMX;

    if (hh == 0 && which == 0 && tid == 0) d_gmax_bits = 0u;

    for (int i = tid; i < NTOK; i += 256) {
        uint32_t b = __float_as_uint(src[(size_t)i * DIMX]);
        uk[i] = (b & 0x80000000u) ? ~b : (b | 0x80000000u);
    }
    __syncthreads();
    if (tid == 0) uk[0] = 0u;
    __syncthreads();

    uint64_t pref = 0;
    int need = MSEL - 1;
#pragma unroll 1
    for (int L = 0; L < 6; L++) {
        int shift = 40 - 8 * L;
        hist[tid] = 0u;
        __syncthreads();
        for (int i = tid; i < NTOK; i += 256) {
            uint64_t c = ((uint64_t)uk[i] << 16) | (uint32_t)(65535 - i);
            if ((c >> (shift + 8)) == pref)
                atomicAdd(&hist[(uint32_t)(c >> shift) & 0xFFu], 1u);
        }
        __syncthreads();
        if (tid == 0) {
            int acc = 0, b = 255;
            for (; b >= 0; b--) {
                int nb = acc + (int)hist[b];
                if (nb >= need) break;
                acc = nb;
            }
            sh_b = b; sh_need = need - acc;
        }
        __syncthreads();
        pref = (pref << 8) | (uint32_t)sh_b;
        need = sh_need;
        __syncthreads();
    }
    uint64_t T = pref;

    if (tid == 0) scnt = 0;
    __syncthreads();
    for (int i = tid; i < NTOK; i += 256) {
        uint64_t c = ((uint64_t)uk[i] << 16) | (uint32_t)(65535 - i);
        if (c >= T) { int p = atomicAdd(&scnt, 1); sel[p] = i; }
    }
    __syncthreads();
    if (tid == 0) sel[MSEL - 1] = 0;
    __syncthreads();

    if (tid < MSEL) {
        int my = sel[tid], rank = 0;
        for (int j = 0; j < MSEL; j++) rank += (sel[j] < my);
        sorted[rank] = my;
    }
    __syncthreads();

    float* dst = (which == 0 ? d_nc : d_nr) + (size_t)hh * MSEL * DIMX;
    for (int i = tid; i < MSEL * DIMX; i += 256) {
        int p = i >> 6, d = i & 63;
        dst[i] = src[(size_t)sorted[p] * DIMX + d];
    }
}

// ======================= kernel 2: kernel_2 = softmax(nr @ nc^T), colsum max =======================
__global__ __launch_bounds__(256) void mker() {
    extern __shared__ float sm[];
    float* As = sm;
    float* Bs = sm + DIMX * PITCH;
    float* cs = sm + 2 * DIMX * PITCH;
    int hh = blockIdx.x, tid = threadIdx.x;
    int ty = tid >> 4, tx = tid & 15;
    load_tileT(As, d_nr + (size_t)hh * MSEL * DIMX, tid);
    load_tileT(Bs, d_nc + (size_t)hh * MSEL * DIMX, tid);
    if (tid < MSEL) cs[tid] = 0.f;
    __syncthreads();

    float acc[8][8] = {};
    mm128(As, Bs, acc, ty, tx);

    float* K2h = d_K2m + (size_t)hh * MSEL * MSEL;
    float colp[8] = {};
#pragma unroll
    for (int i = 0; i < 8; i++) {
        float mx = acc[i][0];
#pragma unroll
        for (int j = 1; j < 8; j++) mx = fmaxf(mx, acc[i][j]);
        mx = grp_max(mx);
        float s = 0.f;
#pragma unroll
        for (int j = 0; j < 8; j++) { acc[i][j] = __expf(acc[i][j] - mx); s += acc[i][j]; }
        s = grp_sum(s);
        float inv = 1.f / s;
#pragma unroll
        for (int j = 0; j < 8; j++) {
            float p = acc[i][j] * inv;
            K2h[(ty*8 + i) * MSEL + tx*8 + j] = p;
            colp[j] += p;
        }
    }
#pragma unroll
    for (int j = 0; j < 8; j++) atomicAdd(&cs[tx*8 + j], colp[j]);
    __syncthreads();
    if (tid < MSEL) atomicMax(&d_gmax_bits, __float_as_uint(cs[tid]));
}

// ======================= MMA1 + online softmax + MMA2 tile body =======================
// product-pass ordering: accumulator reuse distance 16 (MMA1) / 8 (MMA2) instructions.
// per-accumulator product order stays hh -> hl -> lh (bit-identical numerics).
__device__ __forceinline__ void attn_tile_reg(uint32_t sb, int wid, int lane,
                                              float C2[8][4],
                                              float& m0, float& m1, float& s0, float& s1) {
    float C1[16][4] = {};
    int aRow = wid*16 + (lane & 15);
    int aq = lane >> 4, arb = aRow & 7;
    uint32_t aBase = sb + T_A + aRow*128;
    int bRow0 = (lane & 7) + ((lane >> 4) << 3);
    int bq = (lane >> 3) & 1, brb = bRow0 & 7;
    uint32_t bBase = sb + T_B + bRow0*128;

#pragma unroll
    for (int ks = 0; ks < 4; ks++) {
        uint32_t aA = aBase + ((uint32_t)(((2*ks) | aq) ^ arb) << 4);
        uint32_t ah0, ah1, ah2, ah3, al0, al1, al2, al3;
        LDSM_X4(ah0, ah1, ah2, ah3, aA);
        LDSM_X4(al0, al1, al2, al3, aA + 16384);
        // pass 1: ah * bh (all p)
#pragma unroll
        for (int p = 0; p < 8; p++) {
            uint32_t bA = bBase + p*2048 + ((uint32_t)(((2*ks) | bq) ^ brb) << 4);
            uint32_t bh0, bh1, bh2, bh3;
            LDSM_X4(bh0, bh1, bh2, bh3, bA);
            mma_bf16(C1[2*p],   ah0, ah1, ah2, ah3, bh0, bh1);
            mma_bf16(C1[2*p+1], ah0, ah1, ah2, ah3, bh2, bh3);
        }
        // pass 2: ah * bl (all p)
#pragma unroll
        for (int p = 0; p < 8; p++) {
            uint32_t bA = bBase + p*2048 + ((uint32_t)(((2*ks) | bq) ^ brb) << 4);
            uint32_t bl0, bl1, bl2, bl3;
            LDSM_X4(bl0, bl1, bl2, bl3, bA + 16384);
            mma_bf16(C1[2*p],   ah0, ah1, ah2, ah3, bl0, bl1);
            mma_bf16(C1[2*p+1], ah0, ah1, ah2, ah3, bl2, bl3);
        }
        // pass 3: al * bh (all p, bh reloaded)
#pragma unroll
        for (int p = 0; p < 8; p++) {
            uint32_t bA = bBase + p*2048 + ((uint32_t)(((2*ks) | bq) ^ brb) << 4);
            uint32_t bh0, bh1, bh2, bh3;
            LDSM_X4(bh0, bh1, bh2, bh3, bA);
            mma_bf16(C1[2*p],   al0, al1, al2, al3, bh0, bh1);
            mma_bf16(C1[2*p+1], al0, al1, al2, al3, bh2, bh3);
        }
    }

    float cx0 = -3.402823466e38f, cx1 = -3.402823466e38f;
#pragma unroll
    for (int t = 0; t < 16; t++) {
        cx0 = fmaxf(cx0, fmaxf(C1[t][0], C1[t][1]));
        cx1 = fmaxf(cx1, fmaxf(C1[t][2], C1[t][3]));
    }
    cx0 = fmaxf(cx0, __shfl_xor_sync(0xffffffffu, cx0, 1));
    cx0 = fmaxf(cx0, __shfl_xor_sync(0xffffffffu, cx0, 2));
    cx1 = fmaxf(cx1, __shfl_xor_sync(0xffffffffu, cx1, 1));
    cx1 = fmaxf(cx1, __shfl_xor_sync(0xffffffffu, cx1, 2));

    float mn0 = fmaxf(m0, cx0), mn1 = fmaxf(m1, cx1);
    float f0 = __expf(m0 - mn0), f1 = __expf(m1 - mn1);
    float su0 = 0.f, su1 = 0.f;
#pragma unroll
    for (int t = 0; t < 16; t++) {
        C1[t][0] = __expf(C1[t][0] - mn0); C1[t][1] = __expf(C1[t][1] - mn0);
        C1[t][2] = __expf(C1[t][2] - mn1); C1[t][3] = __expf(C1[t][3] - mn1);
        su0 += C1[t][0] + C1[t][1];
        su1 += C1[t][2] + C1[t][3];
    }
    su0 += __shfl_xor_sync(0xffffffffu, su0, 1);
    su0 += __shfl_xor_sync(0xffffffffu, su0, 2);
    su1 += __shfl_xor_sync(0xffffffffu, su1, 1);
    su1 += __shfl_xor_sync(0xffffffffu, su1, 2);
    s0 = s0 * f0 + su0;  s1 = s1 * f1 + su1;
    m0 = mn0;            m1 = mn1;
#pragma unroll
    for (int t = 0; t < 8; t++) {
        C2[t][0] *= f0; C2[t][1] *= f0;
        C2[t][2] *= f1; C2[t][3] *= f1;
    }

    // FA2 register trick: C1 fragments are MMA2 A-fragments directly.
    uint32_t pA0[16], pA1[16], lA0[16], lA1[16];
#pragma unroll
    for (int t = 0; t < 16; t++) {
        pack_split2(C1[t][0], C1[t][1], pA0[t], lA0[t]);
        pack_split2(C1[t][2], C1[t][3], pA1[t], lA1[t]);
    }

    int vRow0 = lane & 15;
    int vq = lane >> 4, vrb = vRow0 & 7;
    uint32_t vBase = sb + T_V + vRow0*128;
#pragma unroll
    for (int ks = 0; ks < 8; ks++) {
        uint32_t ah0 = pA0[2*ks], ah1 = pA1[2*ks], ah2 = pA0[2*ks+1], ah3 = pA1[2*ks+1];
        uint32_t al0 = lA0[2*ks], al1 = lA1[2*ks], al2 = lA0[2*ks+1], al3 = lA1[2*ks+1];
        // pass 1: ph * vh
#pragma unroll
        for (int p = 0; p < 4; p++) {
            uint32_t vA = vBase + ks*2048 + ((uint32_t)(((2*p) | vq) ^ vrb) << 4);
            uint32_t vh0, vh1, vh2, vh3;
            LDSM_X4_T(vh0, vh1, vh2, vh3, vA);
            mma_bf16(C2[2*p],   ah0, ah1, ah2, ah3, vh0, vh1);
            mma_bf16(C2[2*p+1], ah0, ah1, ah2, ah3, vh2, vh3);
        }
        // pass 2: ph * vl
#pragma unroll
        for (int p = 0; p < 4; p++) {
            uint32_t vA = vBase + ks*2048 + ((uint32_t)(((2*p) | vq) ^ vrb) << 4);
            uint32_t vl0, vl1, vl2, vl3;
            LDSM_X4_T(vl0, vl1, vl2, vl3, vA + 16384);
            mma_bf16(C2[2*p],   ah0, ah1, ah2, ah3, vl0, vl1);
            mma_bf16(C2[2*p+1], ah0, ah1, ah2, ah3, vl2, vl3);
        }
        // pass 3: pl * vh (vh reloaded)
#pragma unroll
        for (int p = 0; p < 4; p++) {
            uint32_t vA = vBase + ks*2048 + ((uint32_t)(((2*p) | vq) ^ vrb) << 4);
            uint32_t vh0, vh1, vh2, vh3;
            LDSM_X4_T(vh0, vh1, vh2, vh3, vA);
            mma_bf16(C2[2*p],   al0, al1, al2, al3, vh0, vh1);
            mma_bf16(C2[2*p+1], al0, al1, al2, al3, vh2, vh3);
        }
    }
}

// ======================= kernel 3: flash over 8 chunks, nr staged once, 2 CTAs/SM ==========
__global__ __launch_bounds__(256, 2) void r1ker(const float* __restrict__ Kg,
                                                const float* __restrict__ Vg) {
    extern __shared__ char smem[];
    uint32_t sb = smem_to_u32(smem);
    int hh = blockIdx.x, s = blockIdx.y, tid = threadIdx.x;
    int wid = tid >> 5, lane = tid & 31;

    const float* Kbase = Kg + ((size_t)hh * NTOK + (size_t)s * CHUNKS * MSEL) * DIMX;
    const float* Vbase = Vg + ((size_t)hh * NTOK + (size_t)s * CHUNKS * MSEL) * DIMX;

    stage_sw(smem, T_A, d_nr + (size_t)hh * MSEL * DIMX, tid);   // once — never clobbered

    float C2[8][4] = {};
    float m0 = -3.402823466e38f, m1 = -3.402823466e38f, s0 = 0.f, s1 = 0.f;

#pragma unroll 1
    for (int c = 0; c < CHUNKS; c++) {
        if (c) __syncthreads();
        stage_sw(smem, T_B, Kbase + (size_t)c * MSEL * DIMX, tid);
        stage_sw(smem, T_V, Vbase + (size_t)c * MSEL * DIMX, tid);
        __syncthreads();
        attn_tile_reg(sb, wid, lane, C2, m0, m1, s0, s1);
    }

    size_t base = (size_t)(hh * SPLITS + s) * MSEL;
    int grow0 = wid*16 + (lane >> 2);
    int pcol = (lane & 3) * 2;
    if ((lane & 3) == 0) {
        d_pmax[base + grow0]     = m0;  d_psum[base + grow0]     = s0;
        d_pmax[base + grow0 + 8] = m1;  d_psum[base + grow0 + 8] = s1;
    }
    float* z0 = d_pZ + (base + grow0) * DIMX;
    float* z1 = z0 + 8 * DIMX;
#pragma unroll
    for (int t = 0; t < 8; t++) {
        *reinterpret_cast<float2*>(&z0[t*8 + pcol]) = make_float2(C2[t][0], C2[t][1]);
        *reinterpret_cast<float2*>(&z1[t*8 + pcol]) = make_float2(C2[t][2], C2[t][3]);
    }
}

// ======================= kernel 4: combine splits =======================
__global__ void combiner() {
    int hh = blockIdx.x;
    int r  = blockIdx.y * 16 + threadIdx.y;
    int d  = threadIdx.x * 4;
    const float* pm = d_pmax + (size_t)hh * SPLITS * MSEL;
    const float* ps = d_psum + (size_t)hh * SPLITS * MSEL;
    float M = -3.402823466e38f;
#pragma unroll
    for (int s = 0; s < SPLITS; s++) M = fmaxf(M, pm[s * MSEL + r]);
    float l = 0.f;
    float4 z = make_float4(0.f, 0.f, 0.f, 0.f);
#pragma unroll
    for (int s = 0; s < SPLITS; s++) {
        float w = __expf(pm[s * MSEL + r] - M);
        l += ps[s * MSEL + r] * w;
        float4 pz = *reinterpret_cast<const float4*>(
            &d_pZ[((size_t)(hh * SPLITS + s) * MSEL + r) * DIMX + d]);
        z.x += w * pz.x; z.y += w * pz.y; z.z += w * pz.z; z.w += w * pz.w;
    }
    float inv = 1.f / l;
    *reinterpret_cast<float4*>(&d_Zm[((size_t)hh * MSEL + r) * DIMX + d]) =
        make_float4(z.x * inv, z.y * inv, z.z * inv, z.w * inv);
}

// ======================= Newton-Schulz: single persistent 512-thread TC kernel ==========
__device__ __forceinline__ void stage_split128_512(char* smem, int off,
                                                   const float* __restrict__ g, int tid) {
#pragma unroll
    for (int k = 0; k < 16; k++) {
        int i = tid + k * 512;
        int r = i >> 6, c2 = (i & 63) * 2;
        float2 v = *reinterpret_cast<const float2*>(&g[r*128 + c2]);
        __nv_bfloat16 h0, l0, h1, l1;
        bf16split(v.x, h0, l0); bf16split(v.y, h1, l1);
        int ob = r*272 + c2*2;
        *(__nv_bfloat162*)(smem + off + ob)         = __halves2bfloat162(h0, h1);
        *(__nv_bfloat162*)(smem + off + 34816 + ob) = __halves2bfloat162(l0, l1);
    }
}
__device__ __forceinline__ void stage_split128T(char* smem, int off,
                                                const float* __restrict__ g, float inv, int tid) {
#pragma unroll
    for (int k = 0; k < 16; k++) {
        int i = tid + k * 512;
        int r = i >> 6, c2 = (i & 63) * 2;
        float vx = g[c2*128 + r] * inv;
        float vy = g[(c2+1)*128 + r] * inv;
        __nv_bfloat16 h0, l0, h1, l1;
        bf16split(vx, h0, l0); bf16split(vy, h1, l1);
        int ob = r*272 + c2*2;
        *(__nv_bfloat162*)(smem + off + ob)         = __halves2bfloat162(h0, h1);
        *(__nv_bfloat162*)(smem + off + 34816 + ob) = __halves2bfloat162(l0, l1);
    }
}

__device__ __forceinline__ void mm_tc512(uint32_t sb, int offA, int offB,
                                         int rg, int cg, int lane, float C[8][4]) {
#pragma unroll
    for (int t = 0; t < 8; t++) { C[t][0] = 0.f; C[t][1] = 0.f; C[t][2] = 0.f; C[t][3] = 0.f; }
    uint32_t aH = sb + offA + (rg*16 + (lane & 15))*272 + ((lane >> 4) << 4);
    uint32_t aL = aH + 34816;
    uint32_t bH = sb + offB + (lane & 15)*272 + ((lane >> 4) << 4) + cg*128;
    uint32_t bL = bH + 34816;
#pragma unroll
    for (int ks = 0; ks < 8; ks++) {
        uint32_t ah0, ah1, ah2, ah3, al0, al1, al2, al3;
        LDSM_X4(ah0, ah1, ah2, ah3, aH + ks*32);
        LDSM_X4(al0, al1, al2, al3, aL + ks*32);
        // pass 1: ah*bh
#pragma unroll
        for (int p = 0; p < 4; p++) {
            uint32_t bh0, bh1, bh2, bh3;
            LDSM_X4_T(bh0, bh1, bh2, bh3, bH + ks*4352 + p*32);
            mma_bf16(C[2*p],   ah0, ah1, ah2, ah3, bh0, bh1);
            mma_bf16(C[2*p+1], ah0, ah1, ah2, ah3, bh2, bh3);
        }
        // pass 2: ah*bl
#pragma unroll
        for (int p = 0; p < 4; p++) {
            uint32_t bl0, bl1, bl2, bl3;
            LDSM_X4_T(bl0, bl1, bl2, bl3, bL + ks*4352 + p*32);
            mma_bf16(C[2*p],   ah0, ah1, ah2, ah3, bl0, bl1);
            mma_bf16(C[2*p+1], ah0, ah1, ah2, ah3, bl2, bl3);
        }
        // pass 3: al*bh
#pragma unroll
        for (int p = 0; p < 4; p++) {
            uint32_t bh0, bh1, bh2, bh3;
            LDSM_X4_T(bh0, bh1, bh2, bh3, bH + ks*4352 + p*32);
            mma_bf16(C[2*p],   al0, al1, al2, al3, bh0, bh1);
            mma_bf16(C[2*p+1], al0, al1, al2, al3, bh2, bh3);
        }
    }
}

__device__ __forceinline__ void store_split512(char* smem, int off, int rg, int cg, int lane,
                                               const float C[8][4]) {
    int r0 = rg*16 + (lane >> 2);
    int cb0 = (lane & 3) * 2;
#pragma unroll
    for (int t = 0; t < 8; t++) {
        int cb = (cg*64 + t*8 + cb0) * 2;
        __nv_bfloat16 h0, l0, h1, l1;
        bf16split(C[t][0], h0, l0); bf16split(C[t][1], h1, l1);
        *(__nv_bfloat162*)(smem + off + r0*272 + cb)         = __halves2bfloat162(h0, h1);
        *(__nv_bfloat162*)(smem + off + 34816 + r0*272 + cb) = __halves2bfloat162(l0, l1);
        bf16split(C[t][2], h0, l0); bf16split(C[t][3], h1, l1);
        *(__nv_bfloat162*)(smem + off + (r0+8)*272 + cb)         = __halves2bfloat162(h0, h1);
        *(__nv_bfloat162*)(smem + off + 34816 + (r0+8)*272 + cb) = __halves2bfloat162(l0, l1);
    }
}
__device__ __forceinline__ float read_split(const char* smem, int off, int r, int c) {
    float h = __bfloat162float(*(const __nv_bfloat16*)(smem + off + r*272 + c*2));
    float l = __bfloat162float(*(const __nv_bfloat16*)(smem + off + 34816 + r*272 + c*2));
    return h + l;
}

__global__ __launch_bounds__(512) void newton_persist() {
    extern __shared__ char smem[];
    uint32_t sb = smem_to_u32(smem);
    int hh = blockIdx.x, tid = threadIdx.x;
    int wid = tid >> 5, lane = tid & 31;
    int rg = wid & 7, cg = wid >> 3;
    float R[8][4];
    const float* K2g = d_K2m + (size_t)hh * MSEL * MSEL;
    float inv = 1.f / __uint_as_float(d_gmax_bits);

    stage_split128T(smem, NB_V, K2g, inv, tid);

#pragma unroll 1
    for (int it = 0; it < 6; it++) {
        stage_split128_512(smem, NB_K, K2g, tid);
        __syncthreads();

        mm_tc512(sb, NB_K, NB_V, rg, cg, lane, R);  // KV = K2 @ Vm
        __syncthreads();
        store_split512(smem, NB_K, rg, cg, lane, R);
        __syncthreads();

        mm_tc512(sb, NB_K, NB_K, rg, cg, lane, R);  // P2 = KV @ KV
        __syncthreads();
        store_split512(smem, NB_T, rg, cg, lane, R);
        __syncthreads();

        mm_tc512(sb, NB_K, NB_T, rg, cg, lane, R);  // P3 = KV @ P2
        {
            int r0 = rg*16 + (lane >> 2);
            int cb0 = (lane & 3) * 2;
#pragma unroll
            for (int t = 0; t < 8; t++) {
                int c = cg*64 + t*8 + cb0;
#pragma unroll
                for (int j = 0; j < 4; j++) {
                    int rr = r0 + ((j >> 1) << 3);
                    int cc = c + (j & 1);
                    float kv = read_split(smem, NB_K, rr, cc);
                    float p2 = read_split(smem, NB_T, rr, cc);
                    float e = -15.f*kv + 7.f*p2 - R[t][j];
                    if (rr == cc) e += 13.f;
                    R[t][j] = e;
                }
            }
        }
        __syncthreads();
        store_split512(smem, NB_T, rg, cg, lane, R);
        __syncthreads();

        mm_tc512(sb, NB_V, NB_T, rg, cg, lane, R);  // Vm @ E
        __syncthreads();
#pragma unroll
        for (int t = 0; t < 8; t++) {
            R[t][0] *= 0.25f; R[t][1] *= 0.25f; R[t][2] *= 0.25f; R[t][3] *= 0.25f;
        }
        store_split512(smem, NB_V, rg, cg, lane, R);
        if (it == 5) {
            float* out = d_Vm0 + (size_t)hh * MSEL * MSEL;
            int r0 = rg*16 + (lane >> 2);
            int cb0 = (lane & 3) * 2;
#pragma unroll
            for (int t = 0; t < 8; t++) {
                int c = cg*64 + t*8 + cb0;
                *reinterpret_cast<float2*>(&out[r0*128 + c]) = make_float2(R[t][0], R[t][1]);
                *reinterpret_cast<float2*>(&out[(r0+8)*128 + c]) = make_float2(R[t][2], R[t][3]);
            }
        }
        __syncthreads();
    }
}

// W = Vm_final @ Z  (128x64), grid (48, 2)
__global__ __launch_bounds__(256) void wker() {
    __shared__ float As[32][65];
    __shared__ float Bs[32][65];
    int hh = blockIdx.x;
    const float* Vm = d_Vm0 + (size_t)hh * MSEL * MSEL;
    const float* Z  = d_Zm + (size_t)hh * MSEL * DIMX;
    int r0 = blockIdx.y * 64;
    int tid = threadIdx.x, ty = tid >> 4, tx = tid & 15;
    float acc[4][4] = {};
    for (int kc = 0; kc < MSEL; kc += 32) {
        for (int i = tid; i < 2048; i += 256) {
            int m = i >> 5, k = i & 31;
            As[k][m] = Vm[(r0 + m) * MSEL + kc + k];
        }
        for (int i = tid; i < 2048; i += 256) {
            int k = i >> 6, n = i & 63;
            Bs[k][n] = Z[(kc + k) * DIMX + n];
        }
        __syncthreads();
#pragma unroll 8
        for (int k = 0; k < 32; k++) {
            float a[4], b[4];
#pragma unroll
            for (int i = 0; i < 4; i++) a[i] = As[k][ty*4 + i];
#pragma unroll
            for (int j = 0; j < 4; j++) b[j] = Bs[k][tx*4 + j];
#pragma unroll
            for (int i = 0; i < 4; i++)
#pragma unroll
                for (int j = 0; j < 4; j++)
                    acc[i][j] += a[i] * b[j];
        }
        __syncthreads();
    }
#pragma unroll
    for (int i = 0; i < 4; i++)
#pragma unroll
        for (int j = 0; j < 4; j++)
            d_Wm[(size_t)hh * MSEL * DIMX + (r0 + ty*4 + i) * DIMX + tx*4 + j] = acc[i][j];
}

// ======================= final: X = softmax(Q @ nc^T) @ W, nc/W staged once ==========
__global__ __launch_bounds__(256, 2) void eker(const float* __restrict__ Qg,
                                               float* __restrict__ Xg) {
    extern __shared__ char smem[];
    uint32_t sb = smem_to_u32(smem);
    int hh = blockIdx.x, tid = threadIdx.x;
    int wid = tid >> 5, lane = tid & 31;

    const float* Qbase = Qg + ((size_t)hh * NTOK + (size_t)blockIdx.y * EQC * MSEL) * DIMX;

    stage_sw(smem, T_B, d_nc + (size_t)hh * MSEL * DIMX, tid);   // once
    stage_sw(smem, T_V, d_Wm + (size_t)hh * MSEL * DIMX, tid);   // once

    int grow0 = wid*16 + (lane >> 2);
    int pcol = (lane & 3) * 2;

#pragma unroll 1
    for (int c = 0; c < EQC; c++) {
        if (c) __syncthreads();
        stage_sw(smem, T_A, Qbase + (size_t)c * MSEL * DIMX, tid);
        __syncthreads();

        float C2[8][4] = {};
        float m0 = -3.402823466e38f, m1 = -3.402823466e38f, s0 = 0.f, s1 = 0.f;
        attn_tile_reg(sb, wid, lane, C2, m0, m1, s0, s1);

        float rinv0 = 1.f / s0, rinv1 = 1.f / s1;
        float* x0 = Xg + ((size_t)hh * NTOK + (size_t)(blockIdx.y * EQC + c) * MSEL + grow0) * DIMX;
        float* x1 = x0 + 8 * DIMX;
#pragma unroll
        for (int t = 0; t < 8; t++) {
            *reinterpret_cast<float2*>(&x0[t*8 + pcol]) =
                make_float2(C2[t][0] * rinv0, C2[t][1] * rinv0);
            *reinterpret_cast<float2*>(&x1[t*8 + pcol]) =
                make_float2(C2[t][2] * rinv1, C2[t][3] * rinv1);
        }
    }
}

// ======================= launch (two-stream fork/join DAG) =======================
extern "C" void kernel_launch(void* const* d_in, const int* in_sizes, int n_in,
                              void* d_out, int out_size) {
    const float* Q = (const float*)d_in[0];
    const float* K = (const float*)d_in[1];
    const float* V = (const float*)d_in[2];
    float* X = (float*)d_out;

    const int SMEM_MK = (2 * DIMX * PITCH + MSEL) * 4;
    cudaFuncSetAttribute(mker,           cudaFuncAttributeMaxDynamicSharedMemorySize, SMEM_MK);
    cudaFuncSetAttribute(r1ker,          cudaFuncAttributeMaxDynamicSharedMemorySize, T_SMEM);
    cudaFuncSetAttribute(eker,           cudaFuncAttributeMaxDynamicSharedMemorySize, T_SMEM);
    cudaFuncSetAttribute(newton_persist, cudaFuncAttributeMaxDynamicSharedMemorySize, NB_SZ);

    bool fork = g_streams_ok;
    cudaStream_t sB = fork ? g_s2 : (cudaStream_t)0;

    topk_gather<<<dim3(BHX, 2), 256>>>(Q, K);

    if (fork) {
        cudaEventRecord(g_eA, 0);
        cudaStreamWaitEvent(sB, g_eA, 0);
    }
    // branch B: mker -> persistent newton
    mker<<<BHX, 256, SMEM_MK, sB>>>();
    newton_persist<<<BHX, 512, NB_SZ, sB>>>();
    if (fork) cudaEventRecord(g_eB, sB);

    // branch A: r1ker -> combiner, concurrent with branch B
    r1ker<<<dim3(BHX, SPLITS), 256, T_SMEM>>>(K, V);
    combiner<<<dim3(BHX, 8), dim3(16, 16)>>>();

    if (fork) cudaStreamWaitEvent(0, g_eB, 0);
    wker<<<dim3(BHX, 2), 256>>>();
    eker<<<dim3(BHX, NTOK / MSEL / EQC), 256, T_SMEM>>>(Q, X);
}